// round 1
// baseline (speedup 1.0000x reference)
#include <cuda_runtime.h>

#define N_EMBD 1024
#define N_HEAD 16
#define HEAD_DIM 64
#define BATCH 4
#define SEQ 2048
#define C3 (3 * N_EMBD)

// Scratch (no cudaMalloc allowed): qkv activations and attention output.
__device__ float g_qkv[BATCH * SEQ * C3];      // ~100.7 MB
__device__ float g_att[BATCH * SEQ * N_EMBD];  // ~33.6 MB

// ---------------------------------------------------------------------------
// SGEMM with bias: C[M,N] = A[M,K] @ B[K,N] + bias[N]
// 128x128 block tile, BK=8, 8x8 per-thread tile, 256 threads.
// M,N,K assumed multiples of tile sizes (true here: 8192 x {3072,1024} x 1024).
// ---------------------------------------------------------------------------
__global__ __launch_bounds__(256) void sgemm_bias_kernel(
    const float* __restrict__ A, const float* __restrict__ B,
    const float* __restrict__ bias, float* __restrict__ C,
    int M, int N, int K)
{
    __shared__ float As[8][128];
    __shared__ float Bs[8][132];  // pad to soften bank conflicts

    const int tid = threadIdx.x;
    const int row0 = blockIdx.y * 128;
    const int col0 = blockIdx.x * 128;
    const int tx = tid & 15;   // 0..15 -> 8 cols each
    const int ty = tid >> 4;   // 0..15 -> 8 rows each

    // A tile load: 128x8 floats = 256 float4; one per thread (stored transposed)
    const int ar = tid >> 1;          // 0..127
    const int ak = (tid & 1) * 4;     // 0 or 4
    // B tile load: 8x128 floats = 256 float4; one per thread
    const int bk = tid >> 5;          // 0..7
    const int bc = (tid & 31) * 4;    // 0..124

    float acc[8][8];
    #pragma unroll
    for (int i = 0; i < 8; i++)
        #pragma unroll
        for (int j = 0; j < 8; j++) acc[i][j] = 0.0f;

    const float* Aptr = A + (long)(row0 + ar) * K + ak;
    const float* Bptr = B + (long)bk * N + col0 + bc;

    for (int k0 = 0; k0 < K; k0 += 8) {
        float4 av = *(const float4*)(Aptr + k0);
        float4 bv = *(const float4*)(Bptr + (long)k0 * N);
        As[ak + 0][ar] = av.x;
        As[ak + 1][ar] = av.y;
        As[ak + 2][ar] = av.z;
        As[ak + 3][ar] = av.w;
        *(float4*)&Bs[bk][bc] = bv;
        __syncthreads();

        #pragma unroll
        for (int kk = 0; kk < 8; kk++) {
            float ra[8], rb[8];
            #pragma unroll
            for (int i = 0; i < 8; i++) ra[i] = As[kk][ty * 8 + i];
            #pragma unroll
            for (int j = 0; j < 8; j++) rb[j] = Bs[kk][tx * 8 + j];
            #pragma unroll
            for (int i = 0; i < 8; i++)
                #pragma unroll
                for (int j = 0; j < 8; j++) acc[i][j] += ra[i] * rb[j];
        }
        __syncthreads();
    }

    #pragma unroll
    for (int i = 0; i < 8; i++) {
        const long r = row0 + ty * 8 + i;
        #pragma unroll
        for (int j = 0; j < 8; j += 4) {
            const int c = col0 + tx * 8 + j;
            float4 o;
            o.x = acc[i][j + 0] + bias[c + 0];
            o.y = acc[i][j + 1] + bias[c + 1];
            o.z = acc[i][j + 2] + bias[c + 2];
            o.w = acc[i][j + 3] + bias[c + 3];
            *(float4*)&C[r * N + c] = o;
        }
    }
}

// ---------------------------------------------------------------------------
// Flash attention (causal, fp32). One block = one (b, h, 64-row q-tile).
// K/V tiles of 32 rows. 256 threads: thread t -> row t/4, col-group t%4.
// Online softmax; O accumulated in registers (16 d-values per thread).
// Static smem ~42 KB with conflict-free padding.
// ---------------------------------------------------------------------------
#define QT 64
#define KT 32

__global__ __launch_bounds__(256) void flash_attn_kernel(
    const float* __restrict__ qkv, float* __restrict__ y)
{
    __shared__ float Qs[QT][65];
    __shared__ float Ks[KT][65];
    __shared__ float Vs[KT][65];
    __shared__ float Ps[QT][33];

    const int qt = blockIdx.x;
    const int h  = blockIdx.y;
    const int b  = blockIdx.z;
    const int tid = threadIdx.x;
    const int row = tid >> 2;  // 0..63
    const int g   = tid & 3;   // 0..3
    const int row0 = qt * QT;
    const long base = (long)b * SEQ * C3;
    const int hoff = h * HEAD_DIM;

    // Load Q tile [64 x 64]
    for (int e = tid; e < QT * HEAD_DIM; e += 256) {
        const int r = e >> 6, d = e & 63;
        Qs[r][d] = qkv[base + (long)(row0 + r) * C3 + hoff + d];
    }

    float m = -1e30f, l = 0.0f;
    float o[16];
    #pragma unroll
    for (int i = 0; i < 16; i++) o[i] = 0.0f;

    const int nkt = (row0 + QT) / KT;  // tiles covering cols [0, row0+63]

    for (int kt = 0; kt < nkt; kt++) {
        const int kc0 = kt * KT;
        __syncthreads();  // previous tile's smem reads done
        for (int e = tid; e < KT * HEAD_DIM; e += 256) {
            const int r = e >> 6, d = e & 63;
            const long off = base + (long)(kc0 + r) * C3 + hoff + d;
            Ks[r][d] = qkv[off + N_EMBD];
            Vs[r][d] = qkv[off + 2 * N_EMBD];
        }
        __syncthreads();

        // S = Q K^T for this thread's 8 columns
        float s[8];
        #pragma unroll
        for (int j = 0; j < 8; j++) {
            const int c = g * 8 + j;
            float a = 0.0f;
            #pragma unroll
            for (int d = 0; d < HEAD_DIM; d++) a += Qs[row][d] * Ks[c][d];
            s[j] = (kc0 + c <= row0 + row) ? a * 0.125f : -1e30f;
        }

        // row max across 8 local + 4 sibling threads
        float mt = s[0];
        #pragma unroll
        for (int j = 1; j < 8; j++) mt = fmaxf(mt, s[j]);
        mt = fmaxf(mt, __shfl_xor_sync(0xffffffffu, mt, 1));
        mt = fmaxf(mt, __shfl_xor_sync(0xffffffffu, mt, 2));

        const float mnew = fmaxf(m, mt);
        const float corr = __expf(m - mnew);
        m = mnew;
        l *= corr;
        #pragma unroll
        for (int i = 0; i < 16; i++) o[i] *= corr;

        #pragma unroll
        for (int j = 0; j < 8; j++) {
            const float p = __expf(s[j] - mnew);
            l += p;
            Ps[row][g * 8 + j] = p;
        }
        __syncthreads();

        // O += P @ V (full row of P, this thread's 16 d-columns)
        #pragma unroll
        for (int c = 0; c < KT; c++) {
            const float p = Ps[row][c];
            #pragma unroll
            for (int i = 0; i < 16; i++) o[i] += p * Vs[c][g * 16 + i];
        }
    }

    // total row sum across the 4 sibling threads
    l += __shfl_xor_sync(0xffffffffu, l, 1);
    l += __shfl_xor_sync(0xffffffffu, l, 2);
    const float inv = 1.0f / l;

    float* yp = y + (long)(b * SEQ + row0 + row) * N_EMBD + hoff + g * 16;
    #pragma unroll
    for (int i = 0; i < 16; i += 4) {
        float4 v;
        v.x = o[i + 0] * inv;
        v.y = o[i + 1] * inv;
        v.z = o[i + 2] * inv;
        v.w = o[i + 3] * inv;
        *(float4*)(yp + i) = v;
    }
}

// ---------------------------------------------------------------------------
extern "C" void kernel_launch(void* const* d_in, const int* in_sizes, int n_in,
                              void* d_out, int out_size)
{
    const float* x      = (const float*)d_in[0];
    const float* W_attn = (const float*)d_in[1];
    const float* b_attn = (const float*)d_in[2];
    const float* W_proj = (const float*)d_in[3];
    const float* b_proj = (const float*)d_in[4];
    float* out = (float*)d_out;

    float* qkv = nullptr;
    float* att = nullptr;
    cudaGetSymbolAddress((void**)&qkv, g_qkv);
    cudaGetSymbolAddress((void**)&att, g_att);

    const int M = BATCH * SEQ;  // 8192

    // 1) qkv = x @ W_attn + b_attn   [8192 x 3072]
    sgemm_bias_kernel<<<dim3(C3 / 128, M / 128), 256>>>(
        x, W_attn, b_attn, qkv, M, C3, N_EMBD);

    // 2) causal flash attention -> att [8192 x 1024]
    flash_attn_kernel<<<dim3(SEQ / QT, N_HEAD, BATCH), 256>>>(qkv, att);

    // 3) out = att @ W_proj + b_proj  [8192 x 1024]
    sgemm_bias_kernel<<<dim3(N_EMBD / 128, M / 128), 256>>>(
        att, W_proj, b_proj, out, M, N_EMBD, N_EMBD);
}

// round 3
// speedup vs baseline: 1.1000x; 1.1000x over previous
#include <cuda_runtime.h>
#include <cstdint>

#define N_EMBD 1024
#define N_HEAD 16
#define HEAD_DIM 64
#define BATCH 4
#define SEQ 2048
#define C3 (3 * N_EMBD)

// Scratch (no cudaMalloc allowed)
__device__ float g_qkv[BATCH * SEQ * C3];      // ~100.7 MB
__device__ float g_att[BATCH * SEQ * N_EMBD];  // ~33.6 MB

// ---------------------------------------------------------------------------
// tf32 tensor-core GEMM with bias: C[M,N] = A[M,K] @ B[K,N] + bias[N]
// 128x128 block tile, BK=32, 256 threads = 8 warps, warp tile 32x64.
// mma.sync.aligned.m16n8k8.row.col.f32.tf32.tf32.f32
// Conflict-free smem: As stride 36, Bs stride 136.
// Dims must be multiples of tile sizes (true: 8192 x {3072,1024} x 1024).
// ---------------------------------------------------------------------------
#define BM 128
#define BN 128
#define BKT 32

__device__ __forceinline__ uint32_t f2tf32(float x) {
    uint32_t r;
    asm("cvt.rna.tf32.f32 %0, %1;" : "=r"(r) : "f"(x));
    return r;
}

__device__ __forceinline__ void mma_tf32(float c[4], uint32_t a0, uint32_t a1,
                                         uint32_t a2, uint32_t a3,
                                         uint32_t b0, uint32_t b1) {
    asm volatile(
        "mma.sync.aligned.m16n8k8.row.col.f32.tf32.tf32.f32 "
        "{%0,%1,%2,%3}, {%4,%5,%6,%7}, {%8,%9}, {%0,%1,%2,%3};"
        : "+f"(c[0]), "+f"(c[1]), "+f"(c[2]), "+f"(c[3])
        : "r"(a0), "r"(a1), "r"(a2), "r"(a3), "r"(b0), "r"(b1));
}

__global__ __launch_bounds__(256) void gemm_tf32_bias(
    const float* __restrict__ A, const float* __restrict__ B,
    const float* __restrict__ bias, float* __restrict__ C,
    int M, int N, int K)
{
    __shared__ uint32_t As[BM][36];
    __shared__ uint32_t Bs[BKT][136];

    const int tid = threadIdx.x;
    const int wid = tid >> 5, lane = tid & 31;
    const int wm = wid & 3, wn = wid >> 2;     // warp tile at (wm*32, wn*64)
    const int tg = lane & 3, grp = lane >> 2;
    const int row0 = blockIdx.y * BM, col0 = blockIdx.x * BN;

    // global loaders
    const int arow = tid >> 3;          // 0..31 (+32 per pass, 4 passes)
    const int acol = (tid & 7) * 4;     // k offset within tile
    const int brow = tid >> 5;          // 0..7 (+8 per pass)
    const int bcol = (tid & 31) * 4;

    const float* Ap = A + (long)(row0 + arow) * K + acol;
    const float* Bp = B + (long)brow * N + col0 + bcol;

    float acc[2][8][4];
    #pragma unroll
    for (int mi = 0; mi < 2; mi++)
        #pragma unroll
        for (int ni = 0; ni < 8; ni++)
            #pragma unroll
            for (int e = 0; e < 4; e++) acc[mi][ni][e] = 0.0f;

    float4 ra[4], rb[4];
    const int nt = K / BKT;

    // prefetch tile 0
    #pragma unroll
    for (int p = 0; p < 4; p++) {
        ra[p] = *(const float4*)(Ap + (long)(p * 32) * K);
        rb[p] = *(const float4*)(Bp + (long)(p * 8) * N);
    }

    for (int t = 0; t < nt; t++) {
        // store staged tile to smem (tf32)
        #pragma unroll
        for (int p = 0; p < 4; p++) {
            As[arow + p * 32][acol + 0] = f2tf32(ra[p].x);
            As[arow + p * 32][acol + 1] = f2tf32(ra[p].y);
            As[arow + p * 32][acol + 2] = f2tf32(ra[p].z);
            As[arow + p * 32][acol + 3] = f2tf32(ra[p].w);
            Bs[brow + p * 8][bcol + 0] = f2tf32(rb[p].x);
            Bs[brow + p * 8][bcol + 1] = f2tf32(rb[p].y);
            Bs[brow + p * 8][bcol + 2] = f2tf32(rb[p].z);
            Bs[brow + p * 8][bcol + 3] = f2tf32(rb[p].w);
        }
        __syncthreads();

        // prefetch next tile
        if (t + 1 < nt) {
            #pragma unroll
            for (int p = 0; p < 4; p++) {
                ra[p] = *(const float4*)(Ap + (long)(p * 32) * K + (t + 1) * BKT);
                rb[p] = *(const float4*)(Bp + (long)((t + 1) * BKT + p * 8) * N);
            }
        }

        // compute: 4 k-steps of k=8
        #pragma unroll
        for (int ks = 0; ks < 4; ks++) {
            const int kb = ks * 8;
            uint32_t af[2][4];
            #pragma unroll
            for (int mi = 0; mi < 2; mi++) {
                const int ab = wm * 32 + mi * 16;
                af[mi][0] = As[ab + grp][kb + tg];
                af[mi][1] = As[ab + grp + 8][kb + tg];
                af[mi][2] = As[ab + grp][kb + tg + 4];
                af[mi][3] = As[ab + grp + 8][kb + tg + 4];
            }
            #pragma unroll
            for (int ni = 0; ni < 8; ni++) {
                const int nb = wn * 64 + ni * 8 + grp;
                uint32_t b0 = Bs[kb + tg][nb];
                uint32_t b1 = Bs[kb + tg + 4][nb];
                #pragma unroll
                for (int mi = 0; mi < 2; mi++)
                    mma_tf32(acc[mi][ni], af[mi][0], af[mi][1], af[mi][2],
                             af[mi][3], b0, b1);
            }
        }
        __syncthreads();
    }

    // epilogue with bias
    #pragma unroll
    for (int mi = 0; mi < 2; mi++) {
        const long r0 = row0 + wm * 32 + mi * 16 + grp;
        const long r1 = r0 + 8;
        #pragma unroll
        for (int ni = 0; ni < 8; ni++) {
            const int c = col0 + wn * 64 + ni * 8 + tg * 2;
            const float bv0 = __ldg(&bias[c]);
            const float bv1 = __ldg(&bias[c + 1]);
            float2 o0 = make_float2(acc[mi][ni][0] + bv0, acc[mi][ni][1] + bv1);
            float2 o1 = make_float2(acc[mi][ni][2] + bv0, acc[mi][ni][3] + bv1);
            *(float2*)&C[r0 * N + c] = o0;
            *(float2*)&C[r1 * N + c] = o1;
        }
    }
}

// ---------------------------------------------------------------------------
// Flash attention (causal, fp32). One block = one (b, h, 64-row q-tile).
// 256 threads: thread t -> q-row t/4, group g = t%4.
// Q row held in registers; K cols c = g + 4j; V d-chunks d = q*16 + g*4
// (bank-conflict-free float4 LDS with stride-68 rows).
// ---------------------------------------------------------------------------
#define QT 64
#define KT 32

__global__ __launch_bounds__(256) void flash_attn_kernel(
    const float* __restrict__ qkv, float* __restrict__ y)
{
    __shared__ float Qs[QT][68];
    __shared__ float Ks[KT][68];
    __shared__ float Vs[KT][68];
    __shared__ float Ps[QT][33];

    const int qt = blockIdx.x;
    const int h  = blockIdx.y;
    const int b  = blockIdx.z;
    const int tid = threadIdx.x;
    const int row = tid >> 2;  // 0..63
    const int g   = tid & 3;   // 0..3
    const int row0 = qt * QT;
    const long base = (long)b * SEQ * C3;
    const int hoff = h * HEAD_DIM;

    // Load Q tile [64 x 64] to smem, then hoist this thread's row to regs
    for (int e = tid; e < QT * HEAD_DIM; e += 256) {
        const int r = e >> 6, d = e & 63;
        Qs[r][d] = qkv[base + (long)(row0 + r) * C3 + hoff + d];
    }
    __syncthreads();

    float4 qr[16];
    #pragma unroll
    for (int q = 0; q < 16; q++) qr[q] = *(const float4*)&Qs[row][q * 4];

    float m = -1e30f, l = 0.0f;
    float o[16];
    #pragma unroll
    for (int i = 0; i < 16; i++) o[i] = 0.0f;

    const int nkt = (row0 + QT) / KT;

    for (int kt = 0; kt < nkt; kt++) {
        const int kc0 = kt * KT;
        __syncthreads();  // previous tile's smem reads complete
        for (int e = tid; e < KT * HEAD_DIM; e += 256) {
            const int r = e >> 6, d = e & 63;
            const long off = base + (long)(kc0 + r) * C3 + hoff + d;
            Ks[r][d] = qkv[off + N_EMBD];
            Vs[r][d] = qkv[off + 2 * N_EMBD];
        }
        __syncthreads();

        // S = Q K^T for this thread's 8 columns (c = g + 4j)
        float s[8];
        #pragma unroll
        for (int j = 0; j < 8; j++) {
            const int c = g + 4 * j;
            float a = 0.0f;
            #pragma unroll
            for (int q = 0; q < 16; q++) {
                const float4 kv = *(const float4*)&Ks[c][q * 4];
                a += qr[q].x * kv.x + qr[q].y * kv.y +
                     qr[q].z * kv.z + qr[q].w * kv.w;
            }
            s[j] = (kc0 + c <= row0 + row) ? a * 0.125f : -1e30f;
        }

        // row max across 8 local + 4 sibling threads (g in low lane bits)
        float mt = s[0];
        #pragma unroll
        for (int j = 1; j < 8; j++) mt = fmaxf(mt, s[j]);
        mt = fmaxf(mt, __shfl_xor_sync(0xffffffffu, mt, 1));
        mt = fmaxf(mt, __shfl_xor_sync(0xffffffffu, mt, 2));

        const float mnew = fmaxf(m, mt);
        const float corr = __expf(m - mnew);
        m = mnew;
        l *= corr;
        #pragma unroll
        for (int i = 0; i < 16; i++) o[i] *= corr;

        #pragma unroll
        for (int j = 0; j < 8; j++) {
            const float p = __expf(s[j] - mnew);
            l += p;
            Ps[row][g + 4 * j] = p;
        }
        __syncwarp();  // Ps consumers (same row) are the same warp

        // O += P @ V: this thread owns d = q*16 + g*4 + e
        #pragma unroll
        for (int c = 0; c < KT; c++) {
            const float p = Ps[row][c];
            #pragma unroll
            for (int q = 0; q < 4; q++) {
                const float4 vv = *(const float4*)&Vs[c][q * 16 + g * 4];
                o[q * 4 + 0] += p * vv.x;
                o[q * 4 + 1] += p * vv.y;
                o[q * 4 + 2] += p * vv.z;
                o[q * 4 + 3] += p * vv.w;
            }
        }
    }

    l += __shfl_xor_sync(0xffffffffu, l, 1);
    l += __shfl_xor_sync(0xffffffffu, l, 2);
    const float inv = 1.0f / l;

    float* yp = y + (long)(b * SEQ + row0 + row) * N_EMBD + hoff;
    #pragma unroll
    for (int q = 0; q < 4; q++) {
        float4 v;
        v.x = o[q * 4 + 0] * inv;
        v.y = o[q * 4 + 1] * inv;
        v.z = o[q * 4 + 2] * inv;
        v.w = o[q * 4 + 3] * inv;
        *(float4*)(yp + q * 16 + g * 4) = v;
    }
}

// ---------------------------------------------------------------------------
extern "C" void kernel_launch(void* const* d_in, const int* in_sizes, int n_in,
                              void* d_out, int out_size)
{
    const float* x      = (const float*)d_in[0];
    const float* W_attn = (const float*)d_in[1];
    const float* b_attn = (const float*)d_in[2];
    const float* W_proj = (const float*)d_in[3];
    const float* b_proj = (const float*)d_in[4];
    float* out = (float*)d_out;

    float* qkv = nullptr;
    float* att = nullptr;
    cudaGetSymbolAddress((void**)&qkv, g_qkv);
    cudaGetSymbolAddress((void**)&att, g_att);

    const int M = BATCH * SEQ;  // 8192

    // 1) qkv = x @ W_attn + b_attn   [8192 x 3072]
    gemm_tf32_bias<<<dim3(C3 / BN, M / BM), 256>>>(
        x, W_attn, b_attn, qkv, M, C3, N_EMBD);

    // 2) causal flash attention -> att [8192 x 1024]
    flash_attn_kernel<<<dim3(SEQ / QT, N_HEAD, BATCH), 256>>>(qkv, att);

    // 3) out = att @ W_proj + b_proj  [8192 x 1024]
    gemm_tf32_bias<<<dim3(N_EMBD / BN, M / BM), 256>>>(
        att, W_proj, b_proj, out, M, N_EMBD, N_EMBD);
}

// round 5
// speedup vs baseline: 5.2855x; 4.8048x over previous
#include <cuda_runtime.h>
#include <cstdint>

#define N_EMBD 1024
#define N_HEAD 16
#define HEAD_DIM 64
#define BATCH 4
#define SEQ 2048
#define C3 (3 * N_EMBD)

// Scratch (no cudaMalloc allowed)
__device__ float g_qkv[BATCH * SEQ * C3];      // ~100.7 MB
__device__ float g_att[BATCH * SEQ * N_EMBD];  // ~33.6 MB

__device__ __forceinline__ uint32_t f2tf32(float x) {
    uint32_t r;
    asm("cvt.rna.tf32.f32 %0, %1;" : "=r"(r) : "f"(x));
    return r;
}

__device__ __forceinline__ void mma_tf32(float c[4], uint32_t a0, uint32_t a1,
                                         uint32_t a2, uint32_t a3,
                                         uint32_t b0, uint32_t b1) {
    asm volatile(
        "mma.sync.aligned.m16n8k8.row.col.f32.tf32.tf32.f32 "
        "{%0,%1,%2,%3}, {%4,%5,%6,%7}, {%8,%9}, {%0,%1,%2,%3};"
        : "+f"(c[0]), "+f"(c[1]), "+f"(c[2]), "+f"(c[3])
        : "r"(a0), "r"(a1), "r"(a2), "r"(a3), "r"(b0), "r"(b1));
}

// ---------------------------------------------------------------------------
// tf32 tensor-core GEMM with bias (unchanged from round 3)
// ---------------------------------------------------------------------------
#define BM 128
#define BN 128
#define BKT 32

__global__ __launch_bounds__(256) void gemm_tf32_bias(
    const float* __restrict__ A, const float* __restrict__ B,
    const float* __restrict__ bias, float* __restrict__ C,
    int M, int N, int K)
{
    __shared__ uint32_t As[BM][36];
    __shared__ uint32_t Bs[BKT][136];

    const int tid = threadIdx.x;
    const int wid = tid >> 5, lane = tid & 31;
    const int wm = wid & 3, wn = wid >> 2;
    const int tg = lane & 3, grp = lane >> 2;
    const int row0 = blockIdx.y * BM, col0 = blockIdx.x * BN;

    const int arow = tid >> 3;
    const int acol = (tid & 7) * 4;
    const int brow = tid >> 5;
    const int bcol = (tid & 31) * 4;

    const float* Ap = A + (long)(row0 + arow) * K + acol;
    const float* Bp = B + (long)brow * N + col0 + bcol;

    float acc[2][8][4];
    #pragma unroll
    for (int mi = 0; mi < 2; mi++)
        #pragma unroll
        for (int ni = 0; ni < 8; ni++)
            #pragma unroll
            for (int e = 0; e < 4; e++) acc[mi][ni][e] = 0.0f;

    float4 ra[4], rb[4];
    const int nt = K / BKT;

    #pragma unroll
    for (int p = 0; p < 4; p++) {
        ra[p] = *(const float4*)(Ap + (long)(p * 32) * K);
        rb[p] = *(const float4*)(Bp + (long)(p * 8) * N);
    }

    for (int t = 0; t < nt; t++) {
        #pragma unroll
        for (int p = 0; p < 4; p++) {
            As[arow + p * 32][acol + 0] = f2tf32(ra[p].x);
            As[arow + p * 32][acol + 1] = f2tf32(ra[p].y);
            As[arow + p * 32][acol + 2] = f2tf32(ra[p].z);
            As[arow + p * 32][acol + 3] = f2tf32(ra[p].w);
            Bs[brow + p * 8][bcol + 0] = f2tf32(rb[p].x);
            Bs[brow + p * 8][bcol + 1] = f2tf32(rb[p].y);
            Bs[brow + p * 8][bcol + 2] = f2tf32(rb[p].z);
            Bs[brow + p * 8][bcol + 3] = f2tf32(rb[p].w);
        }
        __syncthreads();

        if (t + 1 < nt) {
            #pragma unroll
            for (int p = 0; p < 4; p++) {
                ra[p] = *(const float4*)(Ap + (long)(p * 32) * K + (t + 1) * BKT);
                rb[p] = *(const float4*)(Bp + (long)((t + 1) * BKT + p * 8) * N);
            }
        }

        #pragma unroll
        for (int ks = 0; ks < 4; ks++) {
            const int kb = ks * 8;
            uint32_t af[2][4];
            #pragma unroll
            for (int mi = 0; mi < 2; mi++) {
                const int ab = wm * 32 + mi * 16;
                af[mi][0] = As[ab + grp][kb + tg];
                af[mi][1] = As[ab + grp + 8][kb + tg];
                af[mi][2] = As[ab + grp][kb + tg + 4];
                af[mi][3] = As[ab + grp + 8][kb + tg + 4];
            }
            #pragma unroll
            for (int ni = 0; ni < 8; ni++) {
                const int nb = wn * 64 + ni * 8 + grp;
                uint32_t b0 = Bs[kb + tg][nb];
                uint32_t b1 = Bs[kb + tg + 4][nb];
                #pragma unroll
                for (int mi = 0; mi < 2; mi++)
                    mma_tf32(acc[mi][ni], af[mi][0], af[mi][1], af[mi][2],
                             af[mi][3], b0, b1);
            }
        }
        __syncthreads();
    }

    #pragma unroll
    for (int mi = 0; mi < 2; mi++) {
        const long r0 = row0 + wm * 32 + mi * 16 + grp;
        const long r1 = r0 + 8;
        #pragma unroll
        for (int ni = 0; ni < 8; ni++) {
            const int c = col0 + wn * 64 + ni * 8 + tg * 2;
            const float bv0 = __ldg(&bias[c]);
            const float bv1 = __ldg(&bias[c + 1]);
            float2 o0 = make_float2(acc[mi][ni][0] + bv0, acc[mi][ni][1] + bv1);
            float2 o1 = make_float2(acc[mi][ni][2] + bv0, acc[mi][ni][3] + bv1);
            *(float2*)&C[r0 * N + c] = o0;
            *(float2*)&C[r1 * N + c] = o1;
        }
    }
}

// ---------------------------------------------------------------------------
// Tensor-core flash attention (causal). One block = (b, h, 64-row q-tile).
// 128 threads = 4 warps, each warp owns 16 q rows (m16 mma slice).
// S = Q K^T via 3-mma tf32 hi/lo compensation (near-fp32 logits).
// O = P V via single tf32 mma.
// Bank-conflict-free strides: Ks/Ps 68, Vs 72.
// ---------------------------------------------------------------------------
#define QT 64
#define KTILE 64
#define KS_S 68
#define VS_S 72
#define PS_S 68
#define ATT_SMEM ((64 * KS_S + 64 * VS_S + 64 * PS_S) * 4)

__global__ __launch_bounds__(128) void flash_attn_tc(
    const float* __restrict__ qkv, float* __restrict__ y)
{
    extern __shared__ float sm[];
    float* Ks = sm;                          // [64][68] raw fp32
    float* Vs = sm + 64 * KS_S;              // [64][72] tf32 bits
    float* Ps = sm + 64 * KS_S + 64 * VS_S;  // [64][68] tf32 bits

    const int qt = blockIdx.x, h = blockIdx.y, b = blockIdx.z;
    const int tid = threadIdx.x;
    const int w = tid >> 5, lane = tid & 31;
    const int grp = lane >> 2, tg = lane & 3;
    const int row0 = qt * QT;
    const long base = (long)b * SEQ * C3;
    const int hoff = h * HEAD_DIM;

    // --- Q fragments (scaled by 1/8), hi/lo split, held in registers ---
    uint32_t qhi[8][4], qlo[8][4];
    {
        const float* qA = qkv + base + (long)(row0 + 16 * w + grp) * C3 + hoff;
        const float* qB = qA + 8 * C3;
        #pragma unroll
        for (int ks = 0; ks < 8; ks++) {
            const int k0 = ks * 8 + tg;
            float f;
            f = qA[k0] * 0.125f;
            qhi[ks][0] = f2tf32(f);
            qlo[ks][0] = f2tf32(f - __uint_as_float(qhi[ks][0]));
            f = qB[k0] * 0.125f;
            qhi[ks][1] = f2tf32(f);
            qlo[ks][1] = f2tf32(f - __uint_as_float(qhi[ks][1]));
            f = qA[k0 + 4] * 0.125f;
            qhi[ks][2] = f2tf32(f);
            qlo[ks][2] = f2tf32(f - __uint_as_float(qhi[ks][2]));
            f = qB[k0 + 4] * 0.125f;
            qhi[ks][3] = f2tf32(f);
            qlo[ks][3] = f2tf32(f - __uint_as_float(qhi[ks][3]));
        }
    }

    float oacc[8][4];
    #pragma unroll
    for (int ni = 0; ni < 8; ni++)
        #pragma unroll
        for (int e = 0; e < 4; e++) oacc[ni][e] = 0.0f;
    float mA = -1e30f, mB = -1e30f, lA = 0.0f, lB = 0.0f;

    for (int kt = 0; kt <= qt; kt++) {
        const int kc0 = kt * KTILE;
        __syncthreads();  // prior tile's smem reads done

        // cooperative K (raw) + V (tf32) tile load
        #pragma unroll
        for (int p = 0; p < 8; p++) {
            const int e = tid + p * 128;
            const int r = e >> 4, c4 = (e & 15) * 4;
            const float* kp = qkv + base + (long)(kc0 + r) * C3 + hoff + N_EMBD + c4;
            const float4 kv = *(const float4*)kp;
            *(float4*)&Ks[r * KS_S + c4] = kv;
            const float4 vv = *(const float4*)(kp + N_EMBD);
            Vs[r * VS_S + c4 + 0] = __uint_as_float(f2tf32(vv.x));
            Vs[r * VS_S + c4 + 1] = __uint_as_float(f2tf32(vv.y));
            Vs[r * VS_S + c4 + 2] = __uint_as_float(f2tf32(vv.z));
            Vs[r * VS_S + c4 + 3] = __uint_as_float(f2tf32(vv.w));
        }
        __syncthreads();

        // --- S = Q K^T (hi/lo compensated tf32) ---
        float sacc[8][4];
        #pragma unroll
        for (int ni = 0; ni < 8; ni++)
            #pragma unroll
            for (int e = 0; e < 4; e++) sacc[ni][e] = 0.0f;

        #pragma unroll
        for (int ks = 0; ks < 8; ks++) {
            const int kb = ks * 8;
            #pragma unroll
            for (int ni = 0; ni < 8; ni++) {
                const int nb = ni * 8 + grp;
                const float f0 = Ks[nb * KS_S + kb + tg];
                const float f1 = Ks[nb * KS_S + kb + tg + 4];
                const uint32_t bh0 = f2tf32(f0), bh1 = f2tf32(f1);
                const uint32_t bl0 = f2tf32(f0 - __uint_as_float(bh0));
                const uint32_t bl1 = f2tf32(f1 - __uint_as_float(bh1));
                mma_tf32(sacc[ni], qhi[ks][0], qhi[ks][1], qhi[ks][2], qhi[ks][3], bh0, bh1);
                mma_tf32(sacc[ni], qhi[ks][0], qhi[ks][1], qhi[ks][2], qhi[ks][3], bl0, bl1);
                mma_tf32(sacc[ni], qlo[ks][0], qlo[ks][1], qlo[ks][2], qlo[ks][3], bh0, bh1);
            }
        }

        // causal mask (diagonal tile only)
        if (kt == qt) {
            const int rA = row0 + 16 * w + grp, rB = rA + 8;
            #pragma unroll
            for (int ni = 0; ni < 8; ni++) {
                const int c0 = kc0 + ni * 8 + 2 * tg;
                if (c0 > rA) sacc[ni][0] = -1e30f;
                if (c0 + 1 > rA) sacc[ni][1] = -1e30f;
                if (c0 > rB) sacc[ni][2] = -1e30f;
                if (c0 + 1 > rB) sacc[ni][3] = -1e30f;
            }
        }

        // --- online softmax (rows grp and grp+8) ---
        float mtA = sacc[0][0], mtB = sacc[0][2];
        #pragma unroll
        for (int ni = 0; ni < 8; ni++) {
            mtA = fmaxf(mtA, fmaxf(sacc[ni][0], sacc[ni][1]));
            mtB = fmaxf(mtB, fmaxf(sacc[ni][2], sacc[ni][3]));
        }
        mtA = fmaxf(mtA, __shfl_xor_sync(0xffffffffu, mtA, 1));
        mtA = fmaxf(mtA, __shfl_xor_sync(0xffffffffu, mtA, 2));
        mtB = fmaxf(mtB, __shfl_xor_sync(0xffffffffu, mtB, 1));
        mtB = fmaxf(mtB, __shfl_xor_sync(0xffffffffu, mtB, 2));

        const float mnA = fmaxf(mA, mtA), mnB = fmaxf(mB, mtB);
        const float cA = __expf(mA - mnA), cB = __expf(mB - mnB);
        mA = mnA; mB = mnB;
        lA *= cA; lB *= cB;
        #pragma unroll
        for (int ni = 0; ni < 8; ni++) {
            oacc[ni][0] *= cA; oacc[ni][1] *= cA;
            oacc[ni][2] *= cB; oacc[ni][3] *= cB;
        }

        float sumA = 0.0f, sumB = 0.0f;
        const int prA = (16 * w + grp) * PS_S;
        const int prB = prA + 8 * PS_S;
        #pragma unroll
        for (int ni = 0; ni < 8; ni++) {
            const float p0 = __expf(sacc[ni][0] - mA);
            const float p1 = __expf(sacc[ni][1] - mA);
            const float p2 = __expf(sacc[ni][2] - mB);
            const float p3 = __expf(sacc[ni][3] - mB);
            sumA += p0 + p1; sumB += p2 + p3;
            const int pc = ni * 8 + 2 * tg;
            uint2 u0 = make_uint2(f2tf32(p0), f2tf32(p1));
            uint2 u1 = make_uint2(f2tf32(p2), f2tf32(p3));
            *(uint2*)&Ps[prA + pc] = u0;
            *(uint2*)&Ps[prB + pc] = u1;
        }
        lA += sumA; lB += sumB;
        __syncwarp();  // P producers/consumers are the same warp

        // --- O += P V (tf32) ---
        #pragma unroll
        for (int ks = 0; ks < 8; ks++) {
            const int kb = ks * 8;
            const uint32_t a0 = __float_as_uint(Ps[prA + kb + tg]);
            const uint32_t a1 = __float_as_uint(Ps[prB + kb + tg]);
            const uint32_t a2 = __float_as_uint(Ps[prA + kb + tg + 4]);
            const uint32_t a3 = __float_as_uint(Ps[prB + kb + tg + 4]);
            #pragma unroll
            for (int ni = 0; ni < 8; ni++) {
                const uint32_t b0 = __float_as_uint(Vs[(kb + tg) * VS_S + ni * 8 + grp]);
                const uint32_t b1 = __float_as_uint(Vs[(kb + tg + 4) * VS_S + ni * 8 + grp]);
                mma_tf32(oacc[ni], a0, a1, a2, a3, b0, b1);
            }
        }
    }

    // --- finalize ---
    lA += __shfl_xor_sync(0xffffffffu, lA, 1);
    lA += __shfl_xor_sync(0xffffffffu, lA, 2);
    lB += __shfl_xor_sync(0xffffffffu, lB, 1);
    lB += __shfl_xor_sync(0xffffffffu, lB, 2);
    const float invA = 1.0f / lA, invB = 1.0f / lB;

    const int rA = row0 + 16 * w + grp, rB = rA + 8;
    float* yA = y + (long)(b * SEQ + rA) * N_EMBD + hoff;
    float* yB = y + (long)(b * SEQ + rB) * N_EMBD + hoff;
    #pragma unroll
    for (int ni = 0; ni < 8; ni++) {
        const int c = ni * 8 + 2 * tg;
        *(float2*)(yA + c) = make_float2(oacc[ni][0] * invA, oacc[ni][1] * invA);
        *(float2*)(yB + c) = make_float2(oacc[ni][2] * invB, oacc[ni][3] * invB);
    }
}

// ---------------------------------------------------------------------------
extern "C" void kernel_launch(void* const* d_in, const int* in_sizes, int n_in,
                              void* d_out, int out_size)
{
    const float* x      = (const float*)d_in[0];
    const float* W_attn = (const float*)d_in[1];
    const float* b_attn = (const float*)d_in[2];
    const float* W_proj = (const float*)d_in[3];
    const float* b_proj = (const float*)d_in[4];
    float* out = (float*)d_out;

    float* qkv = nullptr;
    float* att = nullptr;
    cudaGetSymbolAddress((void**)&qkv, g_qkv);
    cudaGetSymbolAddress((void**)&att, g_att);

    static bool attr_set = false;
    if (!attr_set) {
        cudaFuncSetAttribute(flash_attn_tc,
                             cudaFuncAttributeMaxDynamicSharedMemorySize,
                             ATT_SMEM);
        attr_set = true;
    }

    const int M = BATCH * SEQ;  // 8192

    // 1) qkv = x @ W_attn + b_attn   [8192 x 3072]
    gemm_tf32_bias<<<dim3(C3 / BN, M / BM), 256>>>(
        x, W_attn, b_attn, qkv, M, C3, N_EMBD);

    // 2) causal flash attention (tensor core) -> att [8192 x 1024]
    flash_attn_tc<<<dim3(SEQ / QT, N_HEAD, BATCH), 128, ATT_SMEM>>>(qkv, att);

    // 3) out = att @ W_proj + b_proj  [8192 x 1024]
    gemm_tf32_bias<<<dim3(N_EMBD / BN, M / BM), 256>>>(
        att, W_proj, b_proj, out, M, N_EMBD, N_EMBD);
}